// round 2
// baseline (speedup 1.0000x reference)
#include <cuda_runtime.h>

#define NN 50000
#define NE 800000
#define NF 512
#define NH 64

#define BM 128
#define BN 64
#define BK 32

// Scratch (static device globals; no runtime allocation allowed)
__device__ float g_h  [NN * NH];   // linear output of current layer
__device__ float g_hb [NN * NH];   // post-activation layer-1 output
__device__ float g_agg[NN * NH];   // neighborhood aggregation accumulator
__device__ float g_deg  [NN];
__device__ float g_dinv [NN];
__device__ float g_selfc[NN];
__device__ float g_coef[NE];
__device__ int   g_src [NE];
__device__ int   g_dst [NE];
__device__ int   g_is32;           // 1 if edge_index arrives as int32

// ---- edge_index dtype probe -------------------------------------------------
// If the buffer is genuine int64 with values < 2^31, every odd 32-bit word is 0
// (little-endian). If the harness narrowed it to int32, odd words are node ids
// (random in [0, 50000)) and the chance all 4096 sampled are zero is ~0.
__global__ void k_flag_init() {
    if (blockIdx.x == 0 && threadIdx.x == 0) g_is32 = 0;
}

__global__ void k_detect(const int* __restrict__ ei32) {
    int i = blockIdx.x * blockDim.x + threadIdx.x;
    if (i < 8192 && (i & 1) == 1 && ei32[i] != 0) atomicOr(&g_is32, 1);
}

// ---- normalization precompute ----------------------------------------------
__global__ void k_deg_init() {
    int i = blockIdx.x * blockDim.x + threadIdx.x;
    if (i < NN) g_deg[i] = 1.0f;   // implicit self-loop weight
}

__global__ void k_edge_prep(const void* __restrict__ eiv,
                            const float* __restrict__ ew) {
    int e = blockIdx.x * blockDim.x + threadIdx.x;
    if (e >= NE) return;
    int s, d;
    if (g_is32) {
        const int* p = (const int*)eiv;
        s = p[e];
        d = p[NE + e];
    } else {
        const long long* p = (const long long*)eiv;
        s = (int)p[e];
        d = (int)p[NE + e];
    }
    // Defensive clamp: wrong dtype interpretation becomes a visible rel_err,
    // not a wild-address device fault.
    if ((unsigned)s >= NN) s = 0;
    if ((unsigned)d >= NN) d = 0;
    g_src[e] = s;
    g_dst[e] = d;
    atomicAdd(&g_deg[d], ew[e]);
}

__global__ void k_dinv() {
    int i = blockIdx.x * blockDim.x + threadIdx.x;
    if (i < NN) {
        float dv = rsqrtf(g_deg[i]);
        g_dinv[i]  = dv;
        g_selfc[i] = dv * dv;
    }
}

__global__ void k_coef(const float* __restrict__ ew) {
    int e = blockIdx.x * blockDim.x + threadIdx.x;
    if (e < NE)
        g_coef[e] = g_dinv[g_src[e]] * ew[e] * g_dinv[g_dst[e]];
}

__global__ void k_zero_agg() {
    int i = blockIdx.x * blockDim.x + threadIdx.x;
    if (i < NN * NH) g_agg[i] = 0.0f;
}

// ---- C[M,64] = A[M,K] @ B[K,64], row-major ----------------------------------
// Aext == nullptr -> A = g_hb (layer 2). Output always g_h.
__global__ __launch_bounds__(256)
void k_gemm(const float* __restrict__ Aext, const float* __restrict__ B, int K) {
    const float* A = Aext ? Aext : g_hb;
    float* C = g_h;

    __shared__ float As[BM][BK];
    __shared__ float Bs[BK][BN];

    int tid = threadIdx.x;
    int tx = tid & 15;          // 16 column groups of 4
    int ty = tid >> 4;          // 16 row groups of 8
    int rowbase = ty * 8;
    int colbase = tx * 4;
    int m0 = blockIdx.x * BM;

    float acc[8][4];
#pragma unroll
    for (int r = 0; r < 8; r++)
#pragma unroll
        for (int c = 0; c < 4; c++) acc[r][c] = 0.0f;

    for (int k0 = 0; k0 < K; k0 += BK) {
        // A tile: 128x32 = 1024 float4; 4 per thread
#pragma unroll
        for (int i = 0; i < 4; i++) {
            int q  = tid + i * 256;
            int m  = q >> 3;
            int kk = (q & 7) << 2;
            float4 v = make_float4(0.f, 0.f, 0.f, 0.f);
            int gm = m0 + m;
            if (gm < NN)
                v = *(const float4*)(A + (size_t)gm * K + (k0 + kk));
            *(float4*)(&As[m][kk]) = v;
        }
        // B tile: 32x64 = 512 float4; 2 per thread
#pragma unroll
        for (int i = 0; i < 2; i++) {
            int q  = tid + i * 256;
            int kk = q >> 4;
            int c  = (q & 15) << 2;
            *(float4*)(&Bs[kk][c]) = *(const float4*)(B + (size_t)(k0 + kk) * BN + c);
        }
        __syncthreads();

#pragma unroll
        for (int k = 0; k < BK; k++) {
            float4 b4 = *(float4*)(&Bs[k][colbase]);
#pragma unroll
            for (int r = 0; r < 8; r++) {
                float a = As[rowbase + r][k];
                acc[r][0] += a * b4.x;
                acc[r][1] += a * b4.y;
                acc[r][2] += a * b4.z;
                acc[r][3] += a * b4.w;
            }
        }
        __syncthreads();
    }

#pragma unroll
    for (int r = 0; r < 8; r++) {
        int gm = m0 + rowbase + r;
        if (gm < NN)
            *(float4*)(C + (size_t)gm * BN + colbase) =
                make_float4(acc[r][0], acc[r][1], acc[r][2], acc[r][3]);
    }
}

// ---- one warp per edge: coalesced gather of h[src], scatter-add into agg[dst]
__global__ __launch_bounds__(256)
void k_aggregate() {
    int gw   = (blockIdx.x * blockDim.x + threadIdx.x) >> 5;
    int lane = threadIdx.x & 31;
    if (gw >= NE) return;
    int   s = g_src[gw];
    int   d = g_dst[gw];
    float c = g_coef[gw];
    const float* hs = g_h + (size_t)s * NH;
    float*       ad = g_agg + (size_t)d * NH;
    atomicAdd(ad + lane,      hs[lane]      * c);
    atomicAdd(ad + lane + 32, hs[lane + 32] * c);
}

// ---- out = relu(agg + h*selfc + bias). outp==nullptr -> write g_hb (layer 1).
__global__ void k_finalize(const float* __restrict__ bias, float* __restrict__ outp) {
    int i = blockIdx.x * blockDim.x + threadIdx.x;
    if (i >= NN * NH) return;
    int row = i >> 6;
    float v = g_agg[i] + g_h[i] * g_selfc[row] + bias[i & 63];
    v = v > 0.f ? v : 0.f;
    if (outp) outp[i] = v;
    else      g_hb[i] = v;
}

extern "C" void kernel_launch(void* const* d_in, const int* in_sizes, int n_in,
                              void* d_out, int out_size) {
    const float* x  = (const float*)d_in[0];
    const void*  ei = (const void*)d_in[1];
    const float* ew = (const float*)d_in[2];
    const float* W1 = (const float*)d_in[3];
    const float* b1 = (const float*)d_in[4];
    const float* W2 = (const float*)d_in[5];
    const float* b2 = (const float*)d_in[6];
    float* out = (float*)d_out;

    const int NODE_BLKS = (NN + 255) / 256;
    const int EDGE_BLKS = (NE + 255) / 256;
    const int ELEM_BLKS = (NN * NH + 255) / 256;
    const int GEMM_BLKS = (NN + BM - 1) / BM;
    const int AGG_BLKS  = NE / 8;   // 8 warps (edges) per 256-thread block

    // dtype probe + normalization precompute (shared by both layers)
    k_flag_init<<<1, 32>>>();
    k_detect<<<32, 256>>>((const int*)ei);
    k_deg_init<<<NODE_BLKS, 256>>>();
    k_edge_prep<<<EDGE_BLKS, 256>>>(ei, ew);
    k_dinv<<<NODE_BLKS, 256>>>();
    k_coef<<<EDGE_BLKS, 256>>>(ew);

    // Layer 1
    k_gemm<<<GEMM_BLKS, 256>>>(x, W1, NF);
    k_zero_agg<<<ELEM_BLKS, 256>>>();
    k_aggregate<<<AGG_BLKS, 256>>>();
    k_finalize<<<ELEM_BLKS, 256>>>(b1, nullptr);

    // Layer 2
    k_gemm<<<GEMM_BLKS, 256>>>(nullptr, W2, NH);
    k_zero_agg<<<ELEM_BLKS, 256>>>();
    k_aggregate<<<AGG_BLKS, 256>>>();
    k_finalize<<<ELEM_BLKS, 256>>>(b2, out);
}

// round 5
// speedup vs baseline: 1.1883x; 1.1883x over previous
#include <cuda_runtime.h>
#include <cstdint>

#define NN 50000
#define NE 800000
#define NF 512
#define NH 64

// ---------------- scratch (static device globals; no runtime alloc) ---------
__device__ float    g_h  [NN * NH];   // linear output of current layer
__device__ float    g_hb [NN * NH];   // post-activation layer-1 output
__device__ float    g_agg[NN * NH];   // neighborhood aggregation accumulator
__device__ float    g_deg  [NN];
__device__ float    g_dinv [NN];
__device__ float    g_selfc[NN];
__device__ float    g_coef[NE];
__device__ int      g_src [NE];
__device__ int      g_dst [NE];
__device__ int      g_is32;
__device__ unsigned g_bt1[NF * NH];   // W1 as tf32 bits, row-major [k][n]
__device__ unsigned g_bt2[NH * NH];   // W2 as tf32 bits, row-major [k][n]

__device__ __forceinline__ unsigned tf32_rna(float f) {
    unsigned r;
    asm("cvt.rna.tf32.f32 %0, %1;" : "=r"(r) : "f"(f));
    return r;
}

// ---------------- dtype probe ------------------------------------------------
__global__ void k_flag_init() {
    if (blockIdx.x == 0 && threadIdx.x == 0) g_is32 = 0;
}
__global__ void k_detect(const int* __restrict__ ei32) {
    int i = blockIdx.x * blockDim.x + threadIdx.x;
    if (i < 8192 && (i & 1) == 1 && ei32[i] != 0) atomicOr(&g_is32, 1);
}

// ---------------- normalization precompute -----------------------------------
__global__ void k_deg_init() {
    int i = blockIdx.x * blockDim.x + threadIdx.x;
    if (i < NN) g_deg[i] = 1.0f;
}
__global__ void k_edge_prep(const void* __restrict__ eiv,
                            const float* __restrict__ ew) {
    int e = blockIdx.x * blockDim.x + threadIdx.x;
    if (e >= NE) return;
    int s, d;
    if (g_is32) {
        const int* p = (const int*)eiv;
        s = p[e]; d = p[NE + e];
    } else {
        const long long* p = (const long long*)eiv;
        s = (int)p[e]; d = (int)p[NE + e];
    }
    if ((unsigned)s >= NN) s = 0;
    if ((unsigned)d >= NN) d = 0;
    g_src[e] = s; g_dst[e] = d;
    atomicAdd(&g_deg[d], ew[e]);
}
__global__ void k_dinv() {
    int i = blockIdx.x * blockDim.x + threadIdx.x;
    if (i < NN) {
        float dv = rsqrtf(g_deg[i]);
        g_dinv[i]  = dv;
        g_selfc[i] = dv * dv;
    }
}
__global__ void k_coef(const float* __restrict__ ew) {
    int e = blockIdx.x * blockDim.x + threadIdx.x;
    if (e < NE)
        g_coef[e] = g_dinv[g_src[e]] * ew[e] * g_dinv[g_dst[e]];
}
__global__ void k_zero_agg() {
    int i = blockIdx.x * blockDim.x + threadIdx.x;
    if (i < NN * NH) g_agg[i] = 0.0f;
}

// ---------------- W -> tf32 bits (elementwise; layout unchanged) --------------
__global__ void k_wprep(const float* __restrict__ W1, const float* __restrict__ W2) {
    int i = blockIdx.x * blockDim.x + threadIdx.x;
    if (i < NF * NH)                 g_bt1[i] = tf32_rna(W1[i]);
    else if (i < NF * NH + NH * NH)  g_bt2[i - NF * NH] = tf32_rna(W2[i - NF * NH]);
}

// ---------------- tf32 mma.sync GEMM: C[M,64] = A[M,K] @ B[K,64] --------------
// A fp32 row-major (Aext or g_hb); B selected IN DEVICE CODE (wsel: 1->g_bt1,
// 2->g_bt2) — device-global pointers must never cross the host ABI (on GB300
// ATS the host shadow address silently reads zeros). C = g_h.
// CTA: 256 thr / 8 warps; tile M=128,N=64; warp owns 16x64 strip.
// As[128][36] pad: a-frag bank = (4r+k)&31 = lane  -> conflict-free.
// Bs[32][72]  pad: b-frag bank = (8k+n)&31        -> conflict-free.
__global__ __launch_bounds__(256)
void k_gemm_mma(const float* __restrict__ Aext, int wsel, int K) {
    const float*    A  = Aext ? Aext : g_hb;
    const unsigned* Bt = (wsel == 1) ? g_bt1 : g_bt2;
    __shared__ unsigned As[128 * 36];
    __shared__ unsigned Bs[32 * 72];

    int tid  = threadIdx.x;
    int warp = tid >> 5;
    int lane = tid & 31;
    int grp  = lane >> 2;      // 0..7
    int tig  = lane & 3;       // 0..3
    int m0   = blockIdx.x * 128;

    float acc[8][4];
#pragma unroll
    for (int nt = 0; nt < 8; nt++)
#pragma unroll
        for (int c = 0; c < 4; c++) acc[nt][c] = 0.0f;

    for (int k0 = 0; k0 < K; k0 += 32) {
        __syncthreads();
        // stage A: 128x32 fp32 -> tf32, 1024 float4 slots, 4 per thread
#pragma unroll
        for (int j = 0; j < 4; j++) {
            int q   = tid + j * 256;
            int row = q >> 3;
            int kk  = (q & 7) << 2;
            float4 v = make_float4(0.f, 0.f, 0.f, 0.f);
            int gm = m0 + row;
            if (gm < NN) v = *(const float4*)(A + (size_t)gm * K + k0 + kk);
            unsigned* dst = &As[row * 36 + kk];
            dst[0] = tf32_rna(v.x); dst[1] = tf32_rna(v.y);
            dst[2] = tf32_rna(v.z); dst[3] = tf32_rna(v.w);
        }
        // stage B: 32x64 tf32 bits, 512 uint4 slots, 2 per thread
#pragma unroll
        for (int j = 0; j < 2; j++) {
            int q   = tid + j * 256;
            int row = q >> 4;
            int nn  = (q & 15) << 2;
            uint4 t = *(const uint4*)(Bt + (size_t)(k0 + row) * 64 + nn);
            unsigned* dst = &Bs[row * 72 + nn];
            dst[0] = t.x; dst[1] = t.y; dst[2] = t.z; dst[3] = t.w;
        }
        __syncthreads();

#pragma unroll
        for (int ks = 0; ks < 4; ks++) {
            int r = warp * 16 + grp;
            int k = ks * 8 + tig;
            unsigned a0 = As[r * 36 + k];
            unsigned a1 = As[(r + 8) * 36 + k];
            unsigned a2 = As[r * 36 + k + 4];
            unsigned a3 = As[(r + 8) * 36 + k + 4];
#pragma unroll
            for (int nt = 0; nt < 8; nt++) {
                unsigned b0 = Bs[(ks * 8 + tig) * 72 + nt * 8 + grp];
                unsigned b1 = Bs[(ks * 8 + 4 + tig) * 72 + nt * 8 + grp];
                asm volatile(
                    "mma.sync.aligned.m16n8k8.row.col.f32.tf32.tf32.f32 "
                    "{%0,%1,%2,%3}, {%4,%5,%6,%7}, {%8,%9}, {%0,%1,%2,%3};"
                    : "+f"(acc[nt][0]), "+f"(acc[nt][1]),
                      "+f"(acc[nt][2]), "+f"(acc[nt][3])
                    : "r"(a0), "r"(a1), "r"(a2), "r"(a3), "r"(b0), "r"(b1));
            }
        }
    }

    // store C: rows m0+warp*16+grp (+8), col pairs nt*8 + 2*tig
    int r0 = m0 + warp * 16 + grp;
    int r1 = r0 + 8;
#pragma unroll
    for (int nt = 0; nt < 8; nt++) {
        int cbase = nt * 8 + tig * 2;
        if (r0 < NN)
            *(float2*)(g_h + (size_t)r0 * NH + cbase) = make_float2(acc[nt][0], acc[nt][1]);
        if (r1 < NN)
            *(float2*)(g_h + (size_t)r1 * NH + cbase) = make_float2(acc[nt][2], acc[nt][3]);
    }
}

// ---------------- aggregation: one warp per edge -------------------------------
__global__ __launch_bounds__(256)
void k_aggregate() {
    int gw   = (blockIdx.x * blockDim.x + threadIdx.x) >> 5;
    int lane = threadIdx.x & 31;
    if (gw >= NE) return;
    int   s = g_src[gw];
    int   d = g_dst[gw];
    float c = g_coef[gw];
    const float* hs = g_h + (size_t)s * NH;
    float*       ad = g_agg + (size_t)d * NH;
    atomicAdd(ad + lane,      hs[lane]      * c);
    atomicAdd(ad + lane + 32, hs[lane + 32] * c);
}

// ---------------- epilogue ------------------------------------------------------
__global__ void k_finalize(const float* __restrict__ bias, float* __restrict__ outp) {
    int i = blockIdx.x * blockDim.x + threadIdx.x;
    if (i >= NN * NH) return;
    int row = i >> 6;
    float v = g_agg[i] + g_h[i] * g_selfc[row] + bias[i & 63];
    v = v > 0.f ? v : 0.f;
    if (outp) outp[i] = v;
    else      g_hb[i] = v;
}

extern "C" void kernel_launch(void* const* d_in, const int* in_sizes, int n_in,
                              void* d_out, int out_size) {
    const float* x  = (const float*)d_in[0];
    const void*  ei = (const void*)d_in[1];
    const float* ew = (const float*)d_in[2];
    const float* W1 = (const float*)d_in[3];
    const float* b1 = (const float*)d_in[4];
    const float* W2 = (const float*)d_in[5];
    const float* b2 = (const float*)d_in[6];
    float* out = (float*)d_out;

    const int NODE_BLKS  = (NN + 255) / 256;
    const int EDGE_BLKS  = (NE + 255) / 256;
    const int ELEM_BLKS  = (NN * NH + 255) / 256;
    const int GEMM_BLKS  = (NN + 127) / 128;
    const int AGG_BLKS   = NE / 8;
    const int WPREP_BLKS = (NF * NH + NH * NH + 255) / 256;

    // dtype probe + normalization + weight prep
    k_flag_init<<<1, 32>>>();
    k_detect<<<32, 256>>>((const int*)ei);
    k_deg_init<<<NODE_BLKS, 256>>>();
    k_edge_prep<<<EDGE_BLKS, 256>>>(ei, ew);
    k_dinv<<<NODE_BLKS, 256>>>();
    k_coef<<<EDGE_BLKS, 256>>>(ew);
    k_wprep<<<WPREP_BLKS, 256>>>(W1, W2);

    // Layer 1
    k_gemm_mma<<<GEMM_BLKS, 256>>>(x, 1, NF);
    k_zero_agg<<<ELEM_BLKS, 256>>>();
    k_aggregate<<<AGG_BLKS, 256>>>();
    k_finalize<<<ELEM_BLKS, 256>>>(b1, nullptr);

    // Layer 2
    k_gemm_mma<<<GEMM_BLKS, 256>>>(nullptr, 2, NH);
    k_zero_agg<<<ELEM_BLKS, 256>>>();
    k_aggregate<<<AGG_BLKS, 256>>>();
    k_finalize<<<ELEM_BLKS, 256>>>(b2, out);
}

// round 6
// speedup vs baseline: 1.9430x; 1.6351x over previous
#include <cuda_runtime.h>
#include <cstdint>

#define NN 50000
#define NE 800000
#define NF 512
#define NH 64

// ---------------- scratch (static device globals; no runtime alloc) ---------
__device__ float    g_h  [NN * NH];   // linear output of current layer
__device__ float    g_hb [NN * NH];   // post-activation layer-1 output
__device__ float    g_agg[NN * NH];   // pre-activation accumulator (seeded in GEMM epilogue)
__device__ float    g_deg  [NN];
__device__ float    g_dinv [NN];
__device__ float    g_selfc[NN];
__device__ float    g_coef[NE];
__device__ int      g_src [NE];
__device__ int      g_dst [NE];
__device__ int      g_is32;
__device__ unsigned g_bt1[NF * NH];   // W1 as tf32 bits, row-major [k][n]
__device__ unsigned g_bt2[NH * NH];   // W2 as tf32 bits, row-major [k][n]

__device__ __forceinline__ unsigned tf32_rna(float f) {
    unsigned r;
    asm("cvt.rna.tf32.f32 %0, %1;" : "=r"(r) : "f"(f));
    return r;
}
__device__ __forceinline__ void cp_async16(uint32_t saddr, const void* gptr) {
    asm volatile("cp.async.cg.shared.global [%0], [%1], 16;"
                 :: "r"(saddr), "l"(gptr) : "memory");
}

// ---------------- dtype probe ------------------------------------------------
__global__ void k_flag_init() {
    if (blockIdx.x == 0 && threadIdx.x == 0) g_is32 = 0;
}
__global__ void k_detect(const int* __restrict__ ei32) {
    int i = blockIdx.x * blockDim.x + threadIdx.x;
    if (i < 8192 && (i & 1) == 1 && ei32[i] != 0) atomicOr(&g_is32, 1);
}

// ---------------- normalization precompute -----------------------------------
__global__ void k_deg_init() {
    int i = blockIdx.x * blockDim.x + threadIdx.x;
    if (i < NN) g_deg[i] = 1.0f;
}
__global__ void k_edge_prep(const void* __restrict__ eiv,
                            const float* __restrict__ ew) {
    int e = blockIdx.x * blockDim.x + threadIdx.x;
    if (e >= NE) return;
    int s, d;
    if (g_is32) {
        const int* p = (const int*)eiv;
        s = p[e]; d = p[NE + e];
    } else {
        const long long* p = (const long long*)eiv;
        s = (int)p[e]; d = (int)p[NE + e];
    }
    if ((unsigned)s >= NN) s = 0;
    if ((unsigned)d >= NN) d = 0;
    g_src[e] = s; g_dst[e] = d;
    atomicAdd(&g_deg[d], ew[e]);
}
__global__ void k_dinv() {
    int i = blockIdx.x * blockDim.x + threadIdx.x;
    if (i < NN) {
        float dv = rsqrtf(g_deg[i]);
        g_dinv[i]  = dv;
        g_selfc[i] = dv * dv;
    }
}
__global__ void k_coef(const float* __restrict__ ew) {
    int e = blockIdx.x * blockDim.x + threadIdx.x;
    if (e < NE)
        g_coef[e] = g_dinv[g_src[e]] * ew[e] * g_dinv[g_dst[e]];
}

// ---------------- W -> tf32 bits (elementwise; layout unchanged) --------------
__global__ void k_wprep(const float* __restrict__ W1, const float* __restrict__ W2) {
    int i = blockIdx.x * blockDim.x + threadIdx.x;
    if (i < NF * NH)                 g_bt1[i] = tf32_rna(W1[i]);
    else if (i < NF * NH + NH * NH)  g_bt2[i - NF * NH] = tf32_rna(W2[i - NF * NH]);
}

// ---------------- tf32 mma.sync GEMM + self-loop seed epilogue ----------------
// C[M,64] = A[M,K] @ B[K,64]. A fp32 row-major (Aext or g_hb); B selected in
// device code (never pass device-global pointers through the host ABI — on
// GB300 ATS the host shadow address silently reads zeros).
// Epilogue: g_h = C ; g_agg = C*selfc[row] + bias[col].
// cp.async double-buffered K-chunks of 32. OOB rows clamped (results discarded).
// As pad 36: a-frag bank = (4r+k)&31 = lane -> conflict-free.
// Bs pad 72: b-frag bank = (8k+n)&31        -> conflict-free.
__global__ __launch_bounds__(256)
void k_gemm_mma(const float* __restrict__ Aext, int wsel, int K,
                const float* __restrict__ bias) {
    const float*    A  = Aext ? Aext : g_hb;
    const unsigned* Bt = (wsel == 1) ? g_bt1 : g_bt2;
    __shared__ float    As[2][128 * 36];
    __shared__ unsigned Bs[2][32 * 72];

    int tid  = threadIdx.x;
    int warp = tid >> 5;
    int lane = tid & 31;
    int grp  = lane >> 2;      // 0..7
    int tig  = lane & 3;       // 0..3
    int m0   = blockIdx.x * 128;
    int nc   = K >> 5;

    uint32_t asA = (uint32_t)__cvta_generic_to_shared(&As[0][0]);
    uint32_t asB = (uint32_t)__cvta_generic_to_shared(&Bs[0][0]);

    // stage chunk ch into buffer (ch&1) via cp.async
    auto stage = [&](int ch) {
        int buf = ch & 1;
        int k0  = ch << 5;
        uint32_t ba = asA + buf * (128 * 36 * 4);
        uint32_t bb = asB + buf * (32 * 72 * 4);
#pragma unroll
        for (int j = 0; j < 4; j++) {
            int q   = tid + j * 256;
            int row = q >> 3;
            int kk  = (q & 7) << 2;
            int gm  = m0 + row;
            if (gm >= NN) gm = NN - 1;   // clamp; row's C is discarded
            cp_async16(ba + (row * 36 + kk) * 4, A + (size_t)gm * K + k0 + kk);
        }
#pragma unroll
        for (int j = 0; j < 2; j++) {
            int q   = tid + j * 256;
            int row = q >> 4;
            int nn  = (q & 15) << 2;
            cp_async16(bb + (row * 72 + nn) * 4, Bt + (size_t)(k0 + row) * 64 + nn);
        }
    };

    float acc[8][4];
#pragma unroll
    for (int nt = 0; nt < 8; nt++)
#pragma unroll
        for (int c = 0; c < 4; c++) acc[nt][c] = 0.0f;

    stage(0);
    asm volatile("cp.async.commit_group;" ::: "memory");

    for (int ch = 0; ch < nc; ch++) {
        if (ch + 1 < nc) {
            stage(ch + 1);
            asm volatile("cp.async.commit_group;" ::: "memory");
            asm volatile("cp.async.wait_group 1;" ::: "memory");
        } else {
            asm volatile("cp.async.wait_group 0;" ::: "memory");
        }
        __syncthreads();

        int buf = ch & 1;
        const float*    sa = As[buf];
        const unsigned* sb = Bs[buf];
#pragma unroll
        for (int ks = 0; ks < 4; ks++) {
            int r = warp * 16 + grp;
            int k = ks * 8 + tig;
            unsigned a0 = tf32_rna(sa[r * 36 + k]);
            unsigned a1 = tf32_rna(sa[(r + 8) * 36 + k]);
            unsigned a2 = tf32_rna(sa[r * 36 + k + 4]);
            unsigned a3 = tf32_rna(sa[(r + 8) * 36 + k + 4]);
#pragma unroll
            for (int nt = 0; nt < 8; nt++) {
                unsigned b0 = sb[(ks * 8 + tig) * 72 + nt * 8 + grp];
                unsigned b1 = sb[(ks * 8 + 4 + tig) * 72 + nt * 8 + grp];
                asm volatile(
                    "mma.sync.aligned.m16n8k8.row.col.f32.tf32.tf32.f32 "
                    "{%0,%1,%2,%3}, {%4,%5,%6,%7}, {%8,%9}, {%0,%1,%2,%3};"
                    : "+f"(acc[nt][0]), "+f"(acc[nt][1]),
                      "+f"(acc[nt][2]), "+f"(acc[nt][3])
                    : "r"(a0), "r"(a1), "r"(a2), "r"(a3), "r"(b0), "r"(b1));
            }
        }
        __syncthreads();
    }

    // epilogue: g_h = C; g_agg = C*selfc + bias
    int r0 = m0 + warp * 16 + grp;
    int r1 = r0 + 8;
    float sc0 = (r0 < NN) ? g_selfc[r0] : 0.f;
    float sc1 = (r1 < NN) ? g_selfc[r1] : 0.f;
#pragma unroll
    for (int nt = 0; nt < 8; nt++) {
        int cbase = nt * 8 + tig * 2;
        float bx = bias[cbase], by = bias[cbase + 1];
        if (r0 < NN) {
            *(float2*)(g_h   + (size_t)r0 * NH + cbase) = make_float2(acc[nt][0], acc[nt][1]);
            *(float2*)(g_agg + (size_t)r0 * NH + cbase) =
                make_float2(acc[nt][0] * sc0 + bx, acc[nt][1] * sc0 + by);
        }
        if (r1 < NN) {
            *(float2*)(g_h   + (size_t)r1 * NH + cbase) = make_float2(acc[nt][2], acc[nt][3]);
            *(float2*)(g_agg + (size_t)r1 * NH + cbase) =
                make_float2(acc[nt][2] * sc1 + bx, acc[nt][3] * sc1 + by);
        }
    }
}

// ---------------- aggregation: 16 lanes/edge, red.global.add.v4.f32 -----------
__global__ __launch_bounds__(256)
void k_aggregate() {
    int t = blockIdx.x * 256 + threadIdx.x;
    int e = t >> 4;
    int l = t & 15;
    if (e >= NE) return;
    int   s = g_src[e];
    int   d = g_dst[e];
    float c = g_coef[e];
    float4 h4 = *(const float4*)(g_h + (size_t)s * NH + l * 4);
    float* ad = g_agg + (size_t)d * NH + l * 4;
    asm volatile("red.global.add.v4.f32 [%0], {%1,%2,%3,%4};"
                 :: "l"(ad), "f"(h4.x * c), "f"(h4.y * c),
                    "f"(h4.z * c), "f"(h4.w * c) : "memory");
}

// ---------------- relu: g_agg -> dest (float4) ---------------------------------
__global__ void k_relu(float* __restrict__ outp, int use_out) {
    int i = blockIdx.x * blockDim.x + threadIdx.x;
    if (i >= NN * NH / 4) return;
    float4 v = ((const float4*)g_agg)[i];
    v.x = fmaxf(v.x, 0.f); v.y = fmaxf(v.y, 0.f);
    v.z = fmaxf(v.z, 0.f); v.w = fmaxf(v.w, 0.f);
    float4* dst = use_out ? (float4*)outp : (float4*)g_hb;
    dst[i] = v;
}

extern "C" void kernel_launch(void* const* d_in, const int* in_sizes, int n_in,
                              void* d_out, int out_size) {
    const float* x  = (const float*)d_in[0];
    const void*  ei = (const void*)d_in[1];
    const float* ew = (const float*)d_in[2];
    const float* W1 = (const float*)d_in[3];
    const float* b1 = (const float*)d_in[4];
    const float* W2 = (const float*)d_in[5];
    const float* b2 = (const float*)d_in[6];
    float* out = (float*)d_out;

    const int NODE_BLKS  = (NN + 255) / 256;
    const int EDGE_BLKS  = (NE + 255) / 256;
    const int GEMM_BLKS  = (NN + 127) / 128;
    const int AGG_BLKS   = NE / 16;              // 16 threads per edge
    const int RELU_BLKS  = (NN * NH / 4 + 255) / 256;
    const int WPREP_BLKS = (NF * NH + NH * NH + 255) / 256;

    // dtype probe + normalization + weight prep
    k_flag_init<<<1, 32>>>();
    k_detect<<<32, 256>>>((const int*)ei);
    k_deg_init<<<NODE_BLKS, 256>>>();
    k_edge_prep<<<EDGE_BLKS, 256>>>(ei, ew);
    k_dinv<<<NODE_BLKS, 256>>>();
    k_coef<<<EDGE_BLKS, 256>>>(ew);
    k_wprep<<<WPREP_BLKS, 256>>>(W1, W2);

    // Layer 1: gemm(+seed) -> edge reduce -> relu
    k_gemm_mma<<<GEMM_BLKS, 256>>>(x, 1, NF, b1);
    k_aggregate<<<AGG_BLKS, 256>>>();
    k_relu<<<RELU_BLKS, 256>>>(nullptr, 0);

    // Layer 2
    k_gemm_mma<<<GEMM_BLKS, 256>>>(nullptr, 2, NH, b2);
    k_aggregate<<<AGG_BLKS, 256>>>();
    k_relu<<<RELU_BLKS, 256>>>(out, 1);
}

// round 7
// speedup vs baseline: 2.2225x; 1.1439x over previous
#include <cuda_runtime.h>
#include <cstdint>

#define NN 50000
#define NE 800000
#define NF 512
#define NH 64

// ---------------- scratch (static device globals; no runtime alloc) ---------
__device__ float    g_h   [NN * NH];  // linear output of current layer
__device__ float    g_hb  [NN * NH];  // post-activation layer-1 output
__device__ float    g_agg1[NN * NH];  // edge-sum accumulator, layer 1
__device__ float    g_agg2[NN * NH];  // edge-sum accumulator, layer 2
__device__ float    g_deg  [NN];
__device__ float    g_dinv [NN];
__device__ float    g_selfc[NN];
__device__ float    g_coef[NE];
__device__ int      g_src [NE];
__device__ int      g_dst [NE];
__device__ int      g_is32;
__device__ unsigned g_bt1[NF * NH];   // W1 as tf32 bits, row-major [k][n]
__device__ unsigned g_bt2[NH * NH];   // W2 as tf32 bits, row-major [k][n]

__device__ __forceinline__ unsigned tf32_rna(float f) {
    unsigned r;
    asm("cvt.rna.tf32.f32 %0, %1;" : "=r"(r) : "f"(f));
    return r;
}
__device__ __forceinline__ void cp_async16(uint32_t saddr, const void* gptr) {
    asm volatile("cp.async.cg.shared.global [%0], [%1], 16;"
                 :: "r"(saddr), "l"(gptr) : "memory");
}

// ---------------- prep branch (side stream) -----------------------------------
__global__ void k_prep0() {                 // flag=0, deg=1, zero agg buffers
    int i = blockIdx.x * blockDim.x + threadIdx.x;
    if (i == 0) g_is32 = 0;
    if (i < NN) g_deg[i] = 1.0f;
    if (i < NN * NH / 4) {
        ((float4*)g_agg1)[i] = make_float4(0.f, 0.f, 0.f, 0.f);
        ((float4*)g_agg2)[i] = make_float4(0.f, 0.f, 0.f, 0.f);
    }
}
__global__ void k_detect(const int* __restrict__ ei32) {
    int i = blockIdx.x * blockDim.x + threadIdx.x;
    if (i < 8192 && (i & 1) == 1 && ei32[i] != 0) atomicOr(&g_is32, 1);
}
__global__ void k_edge_prep(const void* __restrict__ eiv,
                            const float* __restrict__ ew) {
    int e = blockIdx.x * blockDim.x + threadIdx.x;
    if (e >= NE) return;
    int s, d;
    if (g_is32) {
        const int* p = (const int*)eiv;
        s = p[e]; d = p[NE + e];
    } else {
        const long long* p = (const long long*)eiv;
        s = (int)p[e]; d = (int)p[NE + e];
    }
    if ((unsigned)s >= NN) s = 0;
    if ((unsigned)d >= NN) d = 0;
    g_src[e] = s; g_dst[e] = d;
    atomicAdd(&g_deg[d], ew[e]);
}
__global__ void k_dinv() {
    int i = blockIdx.x * blockDim.x + threadIdx.x;
    if (i < NN) {
        float dv = rsqrtf(g_deg[i]);
        g_dinv[i]  = dv;
        g_selfc[i] = dv * dv;
    }
}
__global__ void k_coef(const float* __restrict__ ew) {
    int e = blockIdx.x * blockDim.x + threadIdx.x;
    if (e < NE)
        g_coef[e] = g_dinv[g_src[e]] * ew[e] * g_dinv[g_dst[e]];
}

// ---------------- W -> tf32 bits (main stream) ---------------------------------
__global__ void k_wprep(const float* __restrict__ W1, const float* __restrict__ W2) {
    int i = blockIdx.x * blockDim.x + threadIdx.x;
    if (i < NF * NH)                 g_bt1[i] = tf32_rna(W1[i]);
    else if (i < NF * NH + NH * NH)  g_bt2[i - NF * NH] = tf32_rna(W2[i - NF * NH]);
}

// ---------------- tf32 mma.sync GEMM: g_h[M,64] = A[M,K] @ B[K,64] -------------
// A fp32 row-major (Aext or g_hb); B selected in device code (never pass
// device-global pointers through the host ABI — GB300 ATS reads zeros).
// cp.async double-buffered K-chunks of 32. OOB rows clamped (results discarded).
// As pad 36 / Bs pad 72 -> conflict-free fragment loads.
__global__ __launch_bounds__(256)
void k_gemm_mma(const float* __restrict__ Aext, int wsel, int K) {
    const float*    A  = Aext ? Aext : g_hb;
    const unsigned* Bt = (wsel == 1) ? g_bt1 : g_bt2;
    __shared__ float    As[2][128 * 36];
    __shared__ unsigned Bs[2][32 * 72];

    int tid  = threadIdx.x;
    int warp = tid >> 5;
    int lane = tid & 31;
    int grp  = lane >> 2;
    int tig  = lane & 3;
    int m0   = blockIdx.x * 128;
    int nc   = K >> 5;

    uint32_t asA = (uint32_t)__cvta_generic_to_shared(&As[0][0]);
    uint32_t asB = (uint32_t)__cvta_generic_to_shared(&Bs[0][0]);

    auto stage = [&](int ch) {
        int buf = ch & 1;
        int k0  = ch << 5;
        uint32_t ba = asA + buf * (128 * 36 * 4);
        uint32_t bb = asB + buf * (32 * 72 * 4);
#pragma unroll
        for (int j = 0; j < 4; j++) {
            int q   = tid + j * 256;
            int row = q >> 3;
            int kk  = (q & 7) << 2;
            int gm  = m0 + row;
            if (gm >= NN) gm = NN - 1;
            cp_async16(ba + (row * 36 + kk) * 4, A + (size_t)gm * K + k0 + kk);
        }
#pragma unroll
        for (int j = 0; j < 2; j++) {
            int q   = tid + j * 256;
            int row = q >> 4;
            int nn  = (q & 15) << 2;
            cp_async16(bb + (row * 72 + nn) * 4, Bt + (size_t)(k0 + row) * 64 + nn);
        }
    };

    float acc[8][4];
#pragma unroll
    for (int nt = 0; nt < 8; nt++)
#pragma unroll
        for (int c = 0; c < 4; c++) acc[nt][c] = 0.0f;

    stage(0);
    asm volatile("cp.async.commit_group;" ::: "memory");

    for (int ch = 0; ch < nc; ch++) {
        if (ch + 1 < nc) {
            stage(ch + 1);
            asm volatile("cp.async.commit_group;" ::: "memory");
            asm volatile("cp.async.wait_group 1;" ::: "memory");
        } else {
            asm volatile("cp.async.wait_group 0;" ::: "memory");
        }
        __syncthreads();

        int buf = ch & 1;
        const float*    sa = As[buf];
        const unsigned* sb = Bs[buf];
#pragma unroll
        for (int ks = 0; ks < 4; ks++) {
            int r = warp * 16 + grp;
            int k = ks * 8 + tig;
            unsigned a0 = tf32_rna(sa[r * 36 + k]);
            unsigned a1 = tf32_rna(sa[(r + 8) * 36 + k]);
            unsigned a2 = tf32_rna(sa[r * 36 + k + 4]);
            unsigned a3 = tf32_rna(sa[(r + 8) * 36 + k + 4]);
#pragma unroll
            for (int nt = 0; nt < 8; nt++) {
                unsigned b0 = sb[(ks * 8 + tig) * 72 + nt * 8 + grp];
                unsigned b1 = sb[(ks * 8 + 4 + tig) * 72 + nt * 8 + grp];
                asm volatile(
                    "mma.sync.aligned.m16n8k8.row.col.f32.tf32.tf32.f32 "
                    "{%0,%1,%2,%3}, {%4,%5,%6,%7}, {%8,%9}, {%0,%1,%2,%3};"
                    : "+f"(acc[nt][0]), "+f"(acc[nt][1]),
                      "+f"(acc[nt][2]), "+f"(acc[nt][3])
                    : "r"(a0), "r"(a1), "r"(a2), "r"(a3), "r"(b0), "r"(b1));
            }
        }
        __syncthreads();
    }

    int r0 = m0 + warp * 16 + grp;
    int r1 = r0 + 8;
#pragma unroll
    for (int nt = 0; nt < 8; nt++) {
        int cbase = nt * 8 + tig * 2;
        if (r0 < NN)
            *(float2*)(g_h + (size_t)r0 * NH + cbase) = make_float2(acc[nt][0], acc[nt][1]);
        if (r1 < NN)
            *(float2*)(g_h + (size_t)r1 * NH + cbase) = make_float2(acc[nt][2], acc[nt][3]);
    }
}

// ---------------- aggregation: 16 lanes/edge, red.global.add.v4.f32 ------------
__global__ __launch_bounds__(256)
void k_aggregate(int layer) {
    int t = blockIdx.x * 256 + threadIdx.x;
    int e = t >> 4;
    int l = t & 15;
    if (e >= NE) return;
    float* agg = (layer == 1) ? g_agg1 : g_agg2;
    int   s = g_src[e];
    int   d = g_dst[e];
    float c = g_coef[e];
    float4 h4 = *(const float4*)(g_h + (size_t)s * NH + l * 4);
    float* ad = agg + (size_t)d * NH + l * 4;
    asm volatile("red.global.add.v4.f32 [%0], {%1,%2,%3,%4};"
                 :: "l"(ad), "f"(h4.x * c), "f"(h4.y * c),
                    "f"(h4.z * c), "f"(h4.w * c) : "memory");
}

// ---------------- finalize: relu(agg + h*selfc + bias) --------------------------
__global__ void k_finalize(const float* __restrict__ bias, int layer,
                           float* __restrict__ outp) {
    int i = blockIdx.x * blockDim.x + threadIdx.x;
    if (i >= NN * NH / 4) return;
    const float4* agg = (layer == 1) ? (const float4*)g_agg1 : (const float4*)g_agg2;
    int row = i >> 4;
    float sc = g_selfc[row];
    float4 a = agg[i];
    float4 h = ((const float4*)g_h)[i];
    float4 b = *(const float4*)(bias + ((i & 15) << 2));
    float4 v;
    v.x = fmaxf(fmaf(h.x, sc, a.x) + b.x, 0.f);
    v.y = fmaxf(fmaf(h.y, sc, a.y) + b.y, 0.f);
    v.z = fmaxf(fmaf(h.z, sc, a.z) + b.z, 0.f);
    v.w = fmaxf(fmaf(h.w, sc, a.w) + b.w, 0.f);
    float4* dst = (layer == 1) ? (float4*)g_hb : (float4*)outp;
    dst[i] = v;
}

extern "C" void kernel_launch(void* const* d_in, const int* in_sizes, int n_in,
                              void* d_out, int out_size) {
    const float* x  = (const float*)d_in[0];
    const void*  ei = (const void*)d_in[1];
    const float* ew = (const float*)d_in[2];
    const float* W1 = (const float*)d_in[3];
    const float* b1 = (const float*)d_in[4];
    const float* W2 = (const float*)d_in[5];
    const float* b2 = (const float*)d_in[6];
    float* out = (float*)d_out;

    // Fork-join resources: created once on the first (uncaptured) call,
    // reused during graph capture. Fallback to serial if creation failed.
    static cudaStream_t s2 = nullptr;
    static cudaEvent_t  evF = nullptr, evJ = nullptr;
    static int init = 0, have_fork = 0;
    if (!init) {
        init = 1;
        if (cudaStreamCreateWithFlags(&s2, cudaStreamNonBlocking) == cudaSuccess &&
            cudaEventCreateWithFlags(&evF, cudaEventDisableTiming) == cudaSuccess &&
            cudaEventCreateWithFlags(&evJ, cudaEventDisableTiming) == cudaSuccess)
            have_fork = 1;
    }
    cudaStream_t sp = have_fork ? s2 : (cudaStream_t)0;

    const int PREP0_BLKS = (NN * NH / 4 + 255) / 256;
    const int EDGE_BLKS  = (NE + 255) / 256;
    const int NODE_BLKS  = (NN + 255) / 256;
    const int GEMM_BLKS  = (NN + 127) / 128;
    const int AGG_BLKS   = NE / 16;
    const int FIN_BLKS   = (NN * NH / 4 + 255) / 256;
    const int WPREP_BLKS = (NF * NH + NH * NH + 255) / 256;

    // ---- fork: prep branch on s2, GEMM1 branch on origin stream ----
    if (have_fork) {
        cudaEventRecord(evF, 0);
        cudaStreamWaitEvent(s2, evF, 0);
    }
    k_prep0    <<<PREP0_BLKS, 256, 0, sp>>>();
    k_detect   <<<32, 256, 0, sp>>>((const int*)ei);
    k_edge_prep<<<EDGE_BLKS, 256, 0, sp>>>(ei, ew);
    k_dinv     <<<NODE_BLKS, 256, 0, sp>>>();
    k_coef     <<<EDGE_BLKS, 256, 0, sp>>>(ew);

    k_wprep   <<<WPREP_BLKS, 256>>>(W1, W2);
    k_gemm_mma<<<GEMM_BLKS, 256>>>(x, 1, NF);

    if (have_fork) {
        cudaEventRecord(evJ, s2);
        cudaStreamWaitEvent(0, evJ, 0);
    }

    // ---- joined: layer 1 tail + layer 2 ----
    k_aggregate<<<AGG_BLKS, 256>>>(1);
    k_finalize <<<FIN_BLKS, 256>>>(b1, 1, nullptr);

    k_gemm_mma <<<GEMM_BLKS, 256>>>(nullptr, 2, NH);
    k_aggregate<<<AGG_BLKS, 256>>>(2);
    k_finalize <<<FIN_BLKS, 256>>>(b2, 2, out);
}

// round 8
// speedup vs baseline: 2.6257x; 1.1814x over previous
#include <cuda_runtime.h>
#include <cstdint>

#define NN 50000
#define NE 800000
#define NF 512
#define NH 64
#define NCHUNK ((NN + 255) / 256)   // 196 scan chunks

// ---------------- scratch (static device globals; no runtime alloc) ---------
__device__ float    g_h  [NN * NH];  // linear output of current layer
__device__ float    g_hb [NN * NH];  // post-activation layer-1 output
__device__ float    g_deg  [NN];
__device__ float    g_dinv [NN];
__device__ float    g_selfc[NN];
__device__ int      g_src [NE];
__device__ int      g_dst [NE];
__device__ int      g_cnt [NN];      // per-dst edge count (histogram)
__device__ int      g_cur [NN];      // scatter cursors
__device__ int      g_rowptr[NN + 1];
__device__ int      g_part  [NCHUNK];
__device__ int      g_partpre[NCHUNK];
__device__ int      g_csrc [NE];     // CSR: src per slot
__device__ float    g_ccoef[NE];     // CSR: coef per slot
__device__ int      g_is32;
__device__ unsigned g_bt1[NF * NH];  // W1 as tf32 bits, row-major [k][n]
__device__ unsigned g_bt2[NH * NH];  // W2 as tf32 bits, row-major [k][n]

__device__ __forceinline__ unsigned tf32_rna(float f) {
    unsigned r;
    asm("cvt.rna.tf32.f32 %0, %1;" : "=r"(r) : "f"(f));
    return r;
}
__device__ __forceinline__ void cp_async16(uint32_t saddr, const void* gptr) {
    asm volatile("cp.async.cg.shared.global [%0], [%1], 16;"
                 :: "r"(saddr), "l"(gptr) : "memory");
}

// ---------------- prep branch (side stream) -----------------------------------
__global__ void k_prep0() {
    int i = blockIdx.x * blockDim.x + threadIdx.x;
    if (i == 0) g_is32 = 0;
    if (i < NN) { g_deg[i] = 1.0f; g_cnt[i] = 0; g_cur[i] = 0; }
}
__global__ void k_detect(const int* __restrict__ ei32) {
    int i = blockIdx.x * blockDim.x + threadIdx.x;
    if (i < 8192 && (i & 1) == 1 && ei32[i] != 0) atomicOr(&g_is32, 1);
}
__global__ void k_edge_prep(const void* __restrict__ eiv,
                            const float* __restrict__ ew) {
    int e = blockIdx.x * blockDim.x + threadIdx.x;
    if (e >= NE) return;
    int s, d;
    if (g_is32) {
        const int* p = (const int*)eiv;
        s = p[e]; d = p[NE + e];
    } else {
        const long long* p = (const long long*)eiv;
        s = (int)p[e]; d = (int)p[NE + e];
    }
    if ((unsigned)s >= NN) s = 0;
    if ((unsigned)d >= NN) d = 0;
    g_src[e] = s; g_dst[e] = d;
    atomicAdd(&g_deg[d], ew[e]);
    atomicAdd(&g_cnt[d], 1);
}
__global__ void k_dinv() {
    int i = blockIdx.x * blockDim.x + threadIdx.x;
    if (i < NN) {
        float dv = rsqrtf(g_deg[i]);
        g_dinv[i]  = dv;
        g_selfc[i] = dv * dv;
    }
}
// scan stage A: per-256 chunk sums
__global__ void k_scanA() {
    __shared__ int sh[256];
    int i = blockIdx.x * 256 + threadIdx.x;
    sh[threadIdx.x] = (i < NN) ? g_cnt[i] : 0;
    __syncthreads();
    for (int o = 128; o > 0; o >>= 1) {
        if (threadIdx.x < o) sh[threadIdx.x] += sh[threadIdx.x + o];
        __syncthreads();
    }
    if (threadIdx.x == 0) g_part[blockIdx.x] = sh[0];
}
// scan stage B: exclusive scan of NCHUNK partials (single block)
__global__ void k_scanB() {
    __shared__ int sh[256];
    int t = threadIdx.x;
    int v = (t < NCHUNK) ? g_part[t] : 0;
    sh[t] = v;
    __syncthreads();
#pragma unroll
    for (int o = 1; o < 256; o <<= 1) {
        int u = (t >= o) ? sh[t - o] : 0;
        __syncthreads();
        sh[t] += u;
        __syncthreads();
    }
    if (t < NCHUNK) g_partpre[t] = sh[t] - v;   // exclusive
    if (t == 255) g_rowptr[NN] = NE;
}
// scan stage C: local exclusive scan + chunk offset -> rowptr
__global__ void k_scanC() {
    __shared__ int sh[256];
    int i = blockIdx.x * 256 + threadIdx.x;
    int t = threadIdx.x;
    int v = (i < NN) ? g_cnt[i] : 0;
    sh[t] = v;
    __syncthreads();
#pragma unroll
    for (int o = 1; o < 256; o <<= 1) {
        int u = (t >= o) ? sh[t - o] : 0;
        __syncthreads();
        sh[t] += u;
        __syncthreads();
    }
    if (i < NN) g_rowptr[i] = g_partpre[blockIdx.x] + sh[t] - v;
}
// CSR fill: coef computed inline
__global__ void k_csr_fill(const float* __restrict__ ew) {
    int e = blockIdx.x * blockDim.x + threadIdx.x;
    if (e >= NE) return;
    int s = g_src[e], d = g_dst[e];
    int pos = g_rowptr[d] + atomicAdd(&g_cur[d], 1);
    g_csrc[pos]  = s;
    g_ccoef[pos] = g_dinv[s] * ew[e] * g_dinv[d];
}

// ---------------- W -> tf32 bits (main stream) ---------------------------------
__global__ void k_wprep(const float* __restrict__ W1, const float* __restrict__ W2) {
    int i = blockIdx.x * blockDim.x + threadIdx.x;
    if (i < NF * NH)                 g_bt1[i] = tf32_rna(W1[i]);
    else if (i < NF * NH + NH * NH)  g_bt2[i - NF * NH] = tf32_rna(W2[i - NF * NH]);
}

// ---------------- tf32 mma.sync GEMM: g_h[M,64] = A[M,K] @ B[K,64] -------------
// B selected in device code (never pass device-global pointers through the
// host ABI — GB300 ATS silently reads zeros from the host shadow address).
__global__ __launch_bounds__(256)
void k_gemm_mma(const float* __restrict__ Aext, int wsel, int K) {
    const float*    A  = Aext ? Aext : g_hb;
    const unsigned* Bt = (wsel == 1) ? g_bt1 : g_bt2;
    __shared__ float    As[2][128 * 36];
    __shared__ unsigned Bs[2][32 * 72];

    int tid  = threadIdx.x;
    int warp = tid >> 5;
    int lane = tid & 31;
    int grp  = lane >> 2;
    int tig  = lane & 3;
    int m0   = blockIdx.x * 128;
    int nc   = K >> 5;

    uint32_t asA = (uint32_t)__cvta_generic_to_shared(&As[0][0]);
    uint32_t asB = (uint32_t)__cvta_generic_to_shared(&Bs[0][0]);

    auto stage = [&](int ch) {
        int buf = ch & 1;
        int k0  = ch << 5;
        uint32_t ba = asA + buf * (128 * 36 * 4);
        uint32_t bb = asB + buf * (32 * 72 * 4);
#pragma unroll
        for (int j = 0; j < 4; j++) {
            int q   = tid + j * 256;
            int row = q >> 3;
            int kk  = (q & 7) << 2;
            int gm  = m0 + row;
            if (gm >= NN) gm = NN - 1;
            cp_async16(ba + (row * 36 + kk) * 4, A + (size_t)gm * K + k0 + kk);
        }
#pragma unroll
        for (int j = 0; j < 2; j++) {
            int q   = tid + j * 256;
            int row = q >> 4;
            int nn  = (q & 15) << 2;
            cp_async16(bb + (row * 72 + nn) * 4, Bt + (size_t)(k0 + row) * 64 + nn);
        }
    };

    float acc[8][4];
#pragma unroll
    for (int nt = 0; nt < 8; nt++)
#pragma unroll
        for (int c = 0; c < 4; c++) acc[nt][c] = 0.0f;

    stage(0);
    asm volatile("cp.async.commit_group;" ::: "memory");

    for (int ch = 0; ch < nc; ch++) {
        if (ch + 1 < nc) {
            stage(ch + 1);
            asm volatile("cp.async.commit_group;" ::: "memory");
            asm volatile("cp.async.wait_group 1;" ::: "memory");
        } else {
            asm volatile("cp.async.wait_group 0;" ::: "memory");
        }
        __syncthreads();

        int buf = ch & 1;
        const float*    sa = As[buf];
        const unsigned* sb = Bs[buf];
#pragma unroll
        for (int ks = 0; ks < 4; ks++) {
            int r = warp * 16 + grp;
            int k = ks * 8 + tig;
            unsigned a0 = tf32_rna(sa[r * 36 + k]);
            unsigned a1 = tf32_rna(sa[(r + 8) * 36 + k]);
            unsigned a2 = tf32_rna(sa[r * 36 + k + 4]);
            unsigned a3 = tf32_rna(sa[(r + 8) * 36 + k + 4]);
#pragma unroll
            for (int nt = 0; nt < 8; nt++) {
                unsigned b0 = sb[(ks * 8 + tig) * 72 + nt * 8 + grp];
                unsigned b1 = sb[(ks * 8 + 4 + tig) * 72 + nt * 8 + grp];
                asm volatile(
                    "mma.sync.aligned.m16n8k8.row.col.f32.tf32.tf32.f32 "
                    "{%0,%1,%2,%3}, {%4,%5,%6,%7}, {%8,%9}, {%0,%1,%2,%3};"
                    : "+f"(acc[nt][0]), "+f"(acc[nt][1]),
                      "+f"(acc[nt][2]), "+f"(acc[nt][3])
                    : "r"(a0), "r"(a1), "r"(a2), "r"(a3), "r"(b0), "r"(b1));
            }
        }
        __syncthreads();
    }

    int r0 = m0 + warp * 16 + grp;
    int r1 = r0 + 8;
#pragma unroll
    for (int nt = 0; nt < 8; nt++) {
        int cbase = nt * 8 + tig * 2;
        if (r0 < NN)
            *(float2*)(g_h + (size_t)r0 * NH + cbase) = make_float2(acc[nt][0], acc[nt][1]);
        if (r1 < NN)
            *(float2*)(g_h + (size_t)r1 * NH + cbase) = make_float2(acc[nt][2], acc[nt][3]);
    }
}

// ---------------- CSR gather + self-loop + bias + relu (fused) ------------------
// One warp per node; lane l owns cols [2l, 2l+1]. No atomics, single write.
__global__ __launch_bounds__(256)
void k_agg_gather(const float* __restrict__ bias, float* __restrict__ outp,
                  int layer) {
    int node = (blockIdx.x * 256 + threadIdx.x) >> 5;
    int lane = threadIdx.x & 31;
    if (node >= NN) return;
    int beg = g_rowptr[node];
    int end = g_rowptr[node + 1];

    float ax = 0.f, ay = 0.f;
#pragma unroll 2
    for (int i = beg; i < end; i++) {
        int   s = g_csrc[i];
        float c = g_ccoef[i];
        float2 h2 = *(const float2*)(g_h + (size_t)s * NH + lane * 2);
        ax = fmaf(h2.x, c, ax);
        ay = fmaf(h2.y, c, ay);
    }
    float  sc = g_selfc[node];
    float2 hd = *(const float2*)(g_h + (size_t)node * NH + lane * 2);
    float2 b2 = *(const float2*)(bias + lane * 2);
    float2 v;
    v.x = fmaxf(fmaf(hd.x, sc, ax) + b2.x, 0.f);
    v.y = fmaxf(fmaf(hd.y, sc, ay) + b2.y, 0.f);
    float* dst = (layer == 1) ? g_hb : outp;
    *(float2*)(dst + (size_t)node * NH + lane * 2) = v;
}

extern "C" void kernel_launch(void* const* d_in, const int* in_sizes, int n_in,
                              void* d_out, int out_size) {
    const float* x  = (const float*)d_in[0];
    const void*  ei = (const void*)d_in[1];
    const float* ew = (const float*)d_in[2];
    const float* W1 = (const float*)d_in[3];
    const float* b1 = (const float*)d_in[4];
    const float* W2 = (const float*)d_in[5];
    const float* b2 = (const float*)d_in[6];
    float* out = (float*)d_out;

    static cudaStream_t s2 = nullptr;
    static cudaEvent_t  evF = nullptr, evJ = nullptr;
    static int init = 0, have_fork = 0;
    if (!init) {
        init = 1;
        if (cudaStreamCreateWithFlags(&s2, cudaStreamNonBlocking) == cudaSuccess &&
            cudaEventCreateWithFlags(&evF, cudaEventDisableTiming) == cudaSuccess &&
            cudaEventCreateWithFlags(&evJ, cudaEventDisableTiming) == cudaSuccess)
            have_fork = 1;
    }
    cudaStream_t sp = have_fork ? s2 : (cudaStream_t)0;

    const int NODE_BLKS  = (NN + 255) / 256;
    const int EDGE_BLKS  = (NE + 255) / 256;
    const int GEMM_BLKS  = (NN + 127) / 128;
    const int AGG_BLKS   = (NN * 32 + 255) / 256;   // warp per node
    const int WPREP_BLKS = (NF * NH + NH * NH + 255) / 256;

    if (have_fork) {
        cudaEventRecord(evF, 0);
        cudaStreamWaitEvent(s2, evF, 0);
    }
    // launches 1-2 on side stream, 3-4 on main (gemm1 = 4th launch -> profiled)
    k_prep0 <<<NODE_BLKS, 256, 0, sp>>>();
    k_detect<<<32, 256, 0, sp>>>((const int*)ei);

    k_wprep   <<<WPREP_BLKS, 256>>>(W1, W2);
    k_gemm_mma<<<GEMM_BLKS, 256>>>(x, 1, NF);

    // rest of prep branch (hidden under GEMM1)
    k_edge_prep<<<EDGE_BLKS, 256, 0, sp>>>(ei, ew);
    k_dinv     <<<NODE_BLKS, 256, 0, sp>>>();
    k_scanA    <<<NCHUNK, 256, 0, sp>>>();
    k_scanB    <<<1, 256, 0, sp>>>();
    k_scanC    <<<NCHUNK, 256, 0, sp>>>();
    k_csr_fill <<<EDGE_BLKS, 256, 0, sp>>>(ew);

    if (have_fork) {
        cudaEventRecord(evJ, s2);
        cudaStreamWaitEvent(0, evJ, 0);
    }

    // layer 1 tail + layer 2 (agg fuses self-loop + bias + relu)
    k_agg_gather<<<AGG_BLKS, 256>>>(b1, nullptr, 1);
    k_gemm_mma  <<<GEMM_BLKS, 256>>>(nullptr, 2, NH);
    k_agg_gather<<<AGG_BLKS, 256>>>(b2, out, 2);
}

// round 9
// speedup vs baseline: 2.8142x; 1.0718x over previous
#include <cuda_runtime.h>
#include <cstdint>

#define NN 50000
#define NE 800000
#define NF 512
#define NH 64
#define NCHUNK ((NN + 255) / 256)   // 196 scan chunks

// B chunk in fragment-pair layout: 16 blocks (ks,tig) x 136 words
// word(blk, off) = blk*136 + off, off = (nt*8+grp)*2 + khi, data words 0..127
#define BBLK 136
#define BCH  (16 * BBLK)            // 2176 words per chunk (padded)
#define BGCH 2048                   // words per chunk in global g_bt (unpadded)

// ---------------- scratch (static device globals; no runtime alloc) ---------
__device__ float    g_h [NN * NH];   // layer-1 linear output
__device__ float    g_h2[NN * NH];   // layer-2 linear output
__device__ float    g_deg  [NN];
__device__ float    g_dinv [NN];
__device__ float    g_selfc[NN];
__device__ int      g_src [NE];
__device__ int      g_dst [NE];
__device__ int      g_cnt [NN];
__device__ int      g_cur [NN];
__device__ int      g_rowptr[NN + 1];
__device__ int      g_part  [NCHUNK];
__device__ int      g_partpre[NCHUNK];
__device__ int      g_csrc [NE];
__device__ float    g_ccoef[NE];
__device__ int      g_is32;
__device__ unsigned g_bt1[16 * BGCH]; // W1 tf32, fragment-pair chunk layout
__device__ unsigned g_bt2[2  * BGCH]; // W2 tf32, fragment-pair chunk layout

__device__ __forceinline__ unsigned tf32_rna(float f) {
    unsigned r;
    asm("cvt.rna.tf32.f32 %0, %1;" : "=r"(r) : "f"(f));
    return r;
}
__device__ __forceinline__ void cp_async16(uint32_t saddr, const void* gptr) {
    asm volatile("cp.async.cg.shared.global [%0], [%1], 16;"
                 :: "r"(saddr), "l"(gptr) : "memory");
}

// ---------------- prep branch (side stream) -----------------------------------
__global__ void k_prep0() {
    int i = blockIdx.x * blockDim.x + threadIdx.x;
    if (i == 0) g_is32 = 0;
    if (i < NN) { g_deg[i] = 1.0f; g_cnt[i] = 0; g_cur[i] = 0; }
}
__global__ void k_detect(const int* __restrict__ ei32) {
    int i = blockIdx.x * blockDim.x + threadIdx.x;
    if (i < 8192 && (i & 1) == 1 && ei32[i] != 0) atomicOr(&g_is32, 1);
}
__global__ void k_edge_prep(const void* __restrict__ eiv,
                            const float* __restrict__ ew) {
    int e = blockIdx.x * blockDim.x + threadIdx.x;
    if (e >= NE) return;
    int s, d;
    if (g_is32) {
        const int* p = (const int*)eiv;
        s = p[e]; d = p[NE + e];
    } else {
        const long long* p = (const long long*)eiv;
        s = (int)p[e]; d = (int)p[NE + e];
    }
    if ((unsigned)s >= NN) s = 0;
    if ((unsigned)d >= NN) d = 0;
    g_src[e] = s; g_dst[e] = d;
    atomicAdd(&g_deg[d], ew[e]);
    atomicAdd(&g_cnt[d], 1);
}
__global__ void k_dinv() {
    int i = blockIdx.x * blockDim.x + threadIdx.x;
    if (i < NN) {
        float dv = rsqrtf(g_deg[i]);
        g_dinv[i]  = dv;
        g_selfc[i] = dv * dv;
    }
}
__global__ void k_scanA() {
    __shared__ int sh[256];
    int i = blockIdx.x * 256 + threadIdx.x;
    sh[threadIdx.x] = (i < NN) ? g_cnt[i] : 0;
    __syncthreads();
    for (int o = 128; o > 0; o >>= 1) {
        if (threadIdx.x < o) sh[threadIdx.x] += sh[threadIdx.x + o];
        __syncthreads();
    }
    if (threadIdx.x == 0) g_part[blockIdx.x] = sh[0];
}
__global__ void k_scanB() {
    __shared__ int sh[256];
    int t = threadIdx.x;
    int v = (t < NCHUNK) ? g_part[t] : 0;
    sh[t] = v;
    __syncthreads();
#pragma unroll
    for (int o = 1; o < 256; o <<= 1) {
        int u = (t >= o) ? sh[t - o] : 0;
        __syncthreads();
        sh[t] += u;
        __syncthreads();
    }
    if (t < NCHUNK) g_partpre[t] = sh[t] - v;
    if (t == 255) g_rowptr[NN] = NE;
}
__global__ void k_scanC() {
    __shared__ int sh[256];
    int i = blockIdx.x * 256 + threadIdx.x;
    int t = threadIdx.x;
    int v = (i < NN) ? g_cnt[i] : 0;
    sh[t] = v;
    __syncthreads();
#pragma unroll
    for (int o = 1; o < 256; o <<= 1) {
        int u = (t >= o) ? sh[t - o] : 0;
        __syncthreads();
        sh[t] += u;
        __syncthreads();
    }
    if (i < NN) g_rowptr[i] = g_partpre[blockIdx.x] + sh[t] - v;
}
__global__ void k_csr_fill(const float* __restrict__ ew) {
    int e = blockIdx.x * blockDim.x + threadIdx.x;
    if (e >= NE) return;
    int s = g_src[e], d = g_dst[e];
    int pos = g_rowptr[d] + atomicAdd(&g_cur[d], 1);
    g_csrc[pos]  = s;
    g_ccoef[pos] = g_dinv[s] * ew[e] * g_dinv[d];
}

// ---------------- W -> tf32 in fragment-pair chunk layout ----------------------
// word(k, n) = (ch*16 + ks*4 + tig)*128 + n*2 + khi
//   ch=k>>5, kin=k&31, ks=kin>>3, tig=kin&3, khi=(kin>>2)&1
__global__ void k_wprep(const float* __restrict__ W1, const float* __restrict__ W2) {
    int i = blockIdx.x * blockDim.x + threadIdx.x;
    if (i < NF * NH) {
        int k = i >> 6, n = i & 63;
        int ch = k >> 5, kin = k & 31;
        int w = ((ch * 16 + (kin >> 3) * 4 + (kin & 3)) << 7) + n * 2 + ((kin >> 2) & 1);
        g_bt1[w] = tf32_rna(W1[i]);
    } else if (i < NF * NH + NH * NH) {
        int j = i - NF * NH;
        int k = j >> 6, n = j & 63;
        int ch = k >> 5, kin = k & 31;
        int w = ((ch * 16 + (kin >> 3) * 4 + (kin & 3)) << 7) + n * 2 + ((kin >> 2) & 1);
        g_bt2[w] = tf32_rna(W2[j]);
    }
}

// ---------------- GEMM1: g_h[M,64] = x[M,512] @ W1 -----------------------------
// A staged fp32 (pad 36, conflict-free a-frags); B staged in fragment-pair
// layout (BBLK=136 skew -> conflict-free v2 b-frags). cp.async double-buffer.
__global__ __launch_bounds__(256)
void k_gemm_mma(const float* __restrict__ A, int K) {
    const unsigned* Bt = g_bt1;
    __shared__ float    As[2][128 * 36];
    __shared__ unsigned Bs[2][BCH];

    int tid  = threadIdx.x;
    int warp = tid >> 5;
    int lane = tid & 31;
    int grp  = lane >> 2;
    int tig  = lane & 3;
    int m0   = blockIdx.x * 128;
    int nc   = K >> 5;

    uint32_t asA = (uint32_t)__cvta_generic_to_shared(&As[0][0]);
    uint32_t asB = (uint32_t)__cvta_generic_to_shared(&Bs[0][0]);

    auto stage = [&](int ch) {
        int buf = ch & 1;
        int k0  = ch << 5;
        uint32_t ba = asA + buf * (128 * 36 * 4);
        uint32_t bb = asB + buf * (BCH * 4);
#pragma unroll
        for (int j = 0; j < 4; j++) {
            int q   = tid + j * 256;
            int row = q >> 3;
            int kk  = (q & 7) << 2;
            int gm  = m0 + row;
            if (gm >= NN) gm = NN - 1;
            cp_async16(ba + (row * 36 + kk) * 4, A + (size_t)gm * K + k0 + kk);
        }
#pragma unroll
        for (int j = 0; j < 2; j++) {
            int idx = tid + j * 256;         // 512 x 16B transfers
            int blk = idx >> 5;
            int off = (idx & 31) << 2;
            cp_async16(bb + (blk * BBLK + off) * 4,
                       Bt + (size_t)ch * BGCH + blk * 128 + off);
        }
    };

    float acc[8][4];
#pragma unroll
    for (int nt = 0; nt < 8; nt++)
#pragma unroll
        for (int c = 0; c < 4; c++) acc[nt][c] = 0.0f;

    stage(0);
    asm volatile("cp.async.commit_group;" ::: "memory");

    for (int ch = 0; ch < nc; ch++) {
        if (ch + 1 < nc) {
            stage(ch + 1);
            asm volatile("cp.async.commit_group;" ::: "memory");
            asm volatile("cp.async.wait_group 1;" ::: "memory");
        } else {
            asm volatile("cp.async.wait_group 0;" ::: "memory");
        }
        __syncthreads();

        int buf = ch & 1;
        const float*    sa = As[buf];
        const unsigned* sb = Bs[buf];
#pragma unroll
        for (int ks = 0; ks < 4; ks++) {
            int r = warp * 16 + grp;
            int k = ks * 8 + tig;
            unsigned a0 = tf32_rna(sa[r * 36 + k]);
            unsigned a1 = tf32_rna(sa[(r + 8) * 36 + k]);
            unsigned a2 = tf32_rna(sa[r * 36 + k + 4]);
            unsigned a3 = tf32_rna(sa[(r + 8) * 36 + k + 4]);
            const unsigned* bbase = sb + (ks * 4 + tig) * BBLK + grp * 2;
#pragma unroll
            for (int nt = 0; nt < 8; nt++) {
                uint2 bp = *(const uint2*)(bbase + nt * 16);
                asm volatile(
                    "mma.sync.aligned.m16n8k8.row.col.f32.tf32.tf32.f32 "
                    "{%0,%1,%2,%3}, {%4,%5,%6,%7}, {%8,%9}, {%0,%1,%2,%3};"
                    : "+f"(acc[nt][0]), "+f"(acc[nt][1]),
                      "+f"(acc[nt][2]), "+f"(acc[nt][3])
                    : "r"(a0), "r"(a1), "r"(a2), "r"(a3), "r"(bp.x), "r"(bp.y));
            }
        }
        __syncthreads();
    }

    int r0 = m0 + warp * 16 + grp;
    int r1 = r0 + 8;
#pragma unroll
    for (int nt = 0; nt < 8; nt++) {
        int cbase = nt * 8 + tig * 2;
        if (r0 < NN)
            *(float2*)(g_h + (size_t)r0 * NH + cbase) = make_float2(acc[nt][0], acc[nt][1]);
        if (r1 < NN)
            *(float2*)(g_h + (size_t)r1 * NH + cbase) = make_float2(acc[nt][2], acc[nt][3]);
    }
}

// ---------------- fused: agg1 + relu (into smem) + GEMM2 -> g_h2 ---------------
// Phase 1: 16 lanes/node (float4), CSR gather from g_h, relu(agg+selfc*h+b1)
//          written straight into the GEMM-A smem tile (no g_hb round-trip).
// Phase 2: K=64 tf32 MMA vs g_bt2 (prefetched via cp.async during phase 1).
// Output to g_h2 (NOT g_h: other CTAs still gather from g_h).
__global__ __launch_bounds__(256)
void k_fused2(const float* __restrict__ bias) {
    __shared__ float    As[128 * 68];
    __shared__ unsigned Bs[2 * BCH];

    int tid  = threadIdx.x;
    int warp = tid >> 5;
    int lane = tid & 31;
    int grp  = lane >> 2;
    int tig  = lane & 3;
    int m0   = blockIdx.x * 128;

    // prefetch both B2 chunks
    uint32_t asB = (uint32_t)__cvta_generic_to_shared(&Bs[0]);
#pragma unroll
    for (int j = 0; j < 4; j++) {
        int idx = tid + j * 256;            // 1024 x 16B transfers
        int ch  = idx >> 9;
        int r   = idx & 511;
        int blk = r >> 5;
        int off = (r & 31) << 2;
        cp_async16(asB + (ch * BCH + blk * BBLK + off) * 4,
                   g_bt2 + (size_t)ch * BGCH + blk * 128 + off);
    }
    asm volatile("cp.async.commit_group;" ::: "memory");

    // phase 1: aggregate 128 nodes (half-warp each, 8 passes)
    int hw = tid >> 4;
    int l  = tid & 15;
#pragma unroll
    for (int pass = 0; pass < 8; pass++) {
        int node = m0 + pass * 16 + hw;
        float4 v = make_float4(0.f, 0.f, 0.f, 0.f);
        if (node < NN) {
            int beg = g_rowptr[node];
            int end = g_rowptr[node + 1];
            float ax = 0.f, ay = 0.f, az = 0.f, aw = 0.f;
            for (int i = beg; i < end; i++) {
                int   s = g_csrc[i];
                float c = g_ccoef[i];
                float4 h4 = *(const float4*)(g_h + (size_t)s * NH + l * 4);
                ax = fmaf(h4.x, c, ax); ay = fmaf(h4.y, c, ay);
                az = fmaf(h4.z, c, az); aw = fmaf(h4.w, c, aw);
            }
            float  sc = g_selfc[node];
            float4 hd = *(const float4*)(g_h + (size_t)node * NH + l * 4);
            float4 b4 = *(const float4*)(bias + l * 4);
            v.x = fmaxf(fmaf(hd.x, sc, ax) + b4.x, 0.f);
            v.y = fmaxf(fmaf(hd.y, sc, ay) + b4.y, 0.f);
            v.z = fmaxf(fmaf(hd.z, sc, az) + b4.z, 0.f);
            v.w = fmaxf(fmaf(hd.w, sc, aw) + b4.w, 0.f);
        }
        *(float4*)(&As[(pass * 16 + hw) * 68 + l * 4]) = v;
    }
    asm volatile("cp.async.wait_group 0;" ::: "memory");
    __syncthreads();

    // phase 2: GEMM K=64
    float acc[8][4];
#pragma unroll
    for (int nt = 0; nt < 8; nt++)
#pragma unroll
        for (int c = 0; c < 4; c++) acc[nt][c] = 0.0f;

#pragma unroll
    for (int ks = 0; ks < 8; ks++) {
        int ch  = ks >> 2;
        int ksl = ks & 3;
        int r = warp * 16 + grp;
        int k = ks * 8 + tig;
        unsigned a0 = tf32_rna(As[r * 68 + k]);
        unsigned a1 = tf32_rna(As[(r + 8) * 68 + k]);
        unsigned a2 = tf32_rna(As[r * 68 + k + 4]);
        unsigned a3 = tf32_rna(As[(r + 8) * 68 + k + 4]);
        const unsigned* bbase = Bs + ch * BCH + (ksl * 4 + tig) * BBLK + grp * 2;
#pragma unroll
        for (int nt = 0; nt < 8; nt++) {
            uint2 bp = *(const uint2*)(bbase + nt * 16);
            asm volatile(
                "mma.sync.aligned.m16n8k8.row.col.f32.tf32.tf32.f32 "
                "{%0,%1,%2,%3}, {%4,%5,%6,%7}, {%8,%9}, {%0,%1,%2,%3};"
                : "+f"(acc[nt][0]), "+f"(acc[nt][1]),
                  "+f"(acc[nt][2]), "+f"(acc[nt][3])
                : "r"(a0), "r"(a1), "r"(a2), "r"(a3), "r"(bp.x), "r"(bp.y));
        }
    }

    int r0 = m0 + warp * 16 + grp;
    int r1 = r0 + 8;
#pragma unroll
    for (int nt = 0; nt < 8; nt++) {
        int cbase = nt * 8 + tig * 2;
        if (r0 < NN)
            *(float2*)(g_h2 + (size_t)r0 * NH + cbase) = make_float2(acc[nt][0], acc[nt][1]);
        if (r1 < NN)
            *(float2*)(g_h2 + (size_t)r1 * NH + cbase) = make_float2(acc[nt][2], acc[nt][3]);
    }
}

// ---------------- final: agg2 + relu -> out (16 lanes/node, float4) ------------
__global__ __launch_bounds__(256)
void k_agg_final(const float* __restrict__ bias, float* __restrict__ outp) {
    int t    = blockIdx.x * 256 + threadIdx.x;
    int node = t >> 4;
    int l    = t & 15;
    if (node >= NN) return;
    int beg = g_rowptr[node];
    int end = g_rowptr[node + 1];
    float ax = 0.f, ay = 0.f, az = 0.f, aw = 0.f;
    for (int i = beg; i < end; i++) {
        int   s = g_csrc[i];
        float c = g_ccoef[i];
        float4 h4 = *(const float4*)(g_h2 + (size_t)s * NH + l * 4);
        ax = fmaf(h4.x, c, ax); ay = fmaf(h4.y, c, ay);
        az = fmaf(h4.z, c, az); aw = fmaf(h4.w, c, aw);
    }
    float  sc = g_selfc[node];
    float4 hd = *(const float4*)(g_h2 + (size_t)node * NH + l * 4);
    float4 b4 = *(const float4*)(bias + l * 4);
    float4 v;
    v.x = fmaxf(fmaf(hd.x, sc, ax) + b4.x, 0.f);
    v.y = fmaxf(fmaf(hd.y, sc, ay) + b4.y, 0.f);
    v.z = fmaxf(fmaf(hd.z, sc, az) + b4.z, 0.f);
    v.w = fmaxf(fmaf(hd.w, sc, aw) + b4.w, 0.f);
    *(float4*)(outp + (size_t)node * NH + l * 4) = v;
}

extern "C" void kernel_launch(void* const* d_in, const int* in_sizes, int n_in,
                              void* d_out, int out_size) {
    const float* x  = (const float*)d_in[0];
    const void*  ei = (const void*)d_in[1];
    const float* ew = (const float*)d_in[2];
    const float* W1 = (const float*)d_in[3];
    const float* b1 = (const float*)d_in[4];
    const float* W2 = (const float*)d_in[5];
    const float* b2 = (const float*)d_in[6];
    float* out = (float*)d_out;

    static cudaStream_t s2 = nullptr;
    static cudaEvent_t  evF = nullptr, evJ = nullptr;
    static int init = 0, have_fork = 0;
    if (!init) {
        init = 1;
        if (cudaStreamCreateWithFlags(&s2, cudaStreamNonBlocking) == cudaSuccess &&
            cudaEventCreateWithFlags(&evF, cudaEventDisableTiming) == cudaSuccess &&
            cudaEventCreateWithFlags(&evJ, cudaEventDisableTiming) == cudaSuccess)
            have_fork = 1;
    }
    cudaStream_t sp = have_fork ? s2 : (cudaStream_t)0;

    const int NODE_BLKS  = (NN + 255) / 256;
    const int EDGE_BLKS  = (NE + 255) / 256;
    const int GEMM_BLKS  = (NN + 127) / 128;
    const int AGG_BLKS   = (NN * 16 + 255) / 256;
    const int WPREP_BLKS = (NF * NH + NH * NH + 255) / 256;

    if (have_fork) {
        cudaEventRecord(evF, 0);
        cudaStreamWaitEvent(s2, evF, 0);
    }
    k_prep0 <<<NODE_BLKS, 256, 0, sp>>>();
    k_detect<<<32, 256, 0, sp>>>((const int*)ei);

    k_wprep   <<<WPREP_BLKS, 256>>>(W1, W2);
    k_gemm_mma<<<GEMM_BLKS, 256>>>(x, NF);

    // prep chain hidden under GEMM1
    k_edge_prep<<<EDGE_BLKS, 256, 0, sp>>>(ei, ew);
    k_dinv     <<<NODE_BLKS, 256, 0, sp>>>();
    k_scanA    <<<NCHUNK, 256, 0, sp>>>();
    k_scanB    <<<1, 256, 0, sp>>>();
    k_scanC    <<<NCHUNK, 256, 0, sp>>>();
    k_csr_fill <<<EDGE_BLKS, 256, 0, sp>>>(ew);

    if (have_fork) {
        cudaEventRecord(evJ, s2);
        cudaStreamWaitEvent(0, evJ, 0);
    }

    k_fused2   <<<GEMM_BLKS, 256>>>(b1);       // agg1 + relu + GEMM2 -> g_h2
    k_agg_final<<<AGG_BLKS, 256>>>(b2, out);   // agg2 + relu -> out
}